// round 2
// baseline (speedup 1.0000x reference)
#include <cuda_runtime.h>
#include <math.h>

// Problem constants
#define T_TOK 2048
#define D_MOD 1024
#define N_EXP 8
#define H_HID 2048
#define TOPK  2
#define NA    (T_TOK*TOPK)   // 4096 assignments

// GEMM tiling
#define BM 64
#define BN 64
#define BK 16

// -------- device scratch (no cudaMalloc allowed) --------
__device__ int   g_count[N_EXP];
__device__ int   g_offset[N_EXP+1];
__device__ int   g_cursor[N_EXP];
__device__ int   g_tok_e[NA];      // per token: 2 chosen experts
__device__ float g_tok_w[NA];      // per token: 2 gate weights
__device__ int   g_assign_tok[NA]; // expert-segmented token ids
__device__ float g_assign_w[NA];   // expert-segmented gate weights
__device__ float g_Hbuf[(size_t)NA * H_HID]; // 32 MB hidden activations

// -------- init: zero output accumulator + counters --------
__global__ void init_kernel(float* __restrict__ out) {
    int total4 = (T_TOK * D_MOD) / 4;
    float4 z = make_float4(0.f, 0.f, 0.f, 0.f);
    for (int i = blockIdx.x * blockDim.x + threadIdx.x; i < total4;
         i += gridDim.x * blockDim.x) {
        reinterpret_cast<float4*>(out)[i] = z;
    }
    if (blockIdx.x == 0 && threadIdx.x < N_EXP) {
        g_count[threadIdx.x]  = 0;
        g_cursor[threadIdx.x] = 0;
    }
}

// -------- gate: logits, top-2, softmax --------
__global__ void gate_kernel(const float* __restrict__ X,
                            const float* __restrict__ Wg,
                            const float* __restrict__ bg,
                            float* __restrict__ out_idx) {
    int warp = (blockIdx.x * blockDim.x + threadIdx.x) >> 5;
    int lane = threadIdx.x & 31;
    if (warp >= T_TOK) return;
    const float* xr = X + (size_t)warp * D_MOD;

    float acc[N_EXP];
#pragma unroll
    for (int e = 0; e < N_EXP; e++) acc[e] = 0.f;

    for (int i = lane; i < D_MOD; i += 32) {
        float xv = xr[i];
        const float* wr = Wg + (size_t)i * N_EXP;
#pragma unroll
        for (int e = 0; e < N_EXP; e++) acc[e] += xv * wr[e];
    }
#pragma unroll
    for (int e = 0; e < N_EXP; e++) {
#pragma unroll
        for (int o = 16; o > 0; o >>= 1)
            acc[e] += __shfl_xor_sync(0xFFFFFFFFu, acc[e], o);
    }

    if (lane == 0) {
        float l[N_EXP];
#pragma unroll
        for (int e = 0; e < N_EXP; e++) l[e] = acc[e] + bg[e];

        float v0 = -1e30f, v1 = -1e30f;
        int   i0 = 0,      i1 = 0;
#pragma unroll
        for (int e = 0; e < N_EXP; e++) {
            if (l[e] > v0)      { v1 = v0; i1 = i0; v0 = l[e]; i0 = e; }
            else if (l[e] > v1) { v1 = l[e]; i1 = e; }
        }
        float s  = expf(v1 - v0);     // <= 1
        float w0 = 1.f / (1.f + s);
        float w1 = s * w0;

        int t = warp;
        g_tok_e[t*2+0] = i0;  g_tok_w[t*2+0] = w0;
        g_tok_e[t*2+1] = i1;  g_tok_w[t*2+1] = w1;
        atomicAdd(&g_count[i0], 1);
        atomicAdd(&g_count[i1], 1);
        if (out_idx) {
            out_idx[t*2+0] = (float)i0;
            out_idx[t*2+1] = (float)i1;
        }
    }
}

// -------- prefix sum of expert counts --------
__global__ void offsets_kernel() {
    if (threadIdx.x == 0 && blockIdx.x == 0) {
        int run = 0;
        g_offset[0] = 0;
#pragma unroll
        for (int e = 0; e < N_EXP; e++) { run += g_count[e]; g_offset[e+1] = run; }
    }
}

// -------- scatter token ids into expert segments --------
__global__ void scatter_kernel() {
    int t = blockIdx.x * blockDim.x + threadIdx.x;
    if (t >= T_TOK) return;
#pragma unroll
    for (int j = 0; j < TOPK; j++) {
        int e = g_tok_e[t*2+j];
        int pos = atomicAdd(&g_cursor[e], 1);
        int slot = g_offset[e] + pos;
        g_assign_tok[slot] = t;
        g_assign_w[slot]   = g_tok_w[t*2+j];
    }
}

// -------- FFN1: H = gelu(Xg @ W1[e] + b1[e]) --------
__global__ __launch_bounds__(256)
void gemm1_kernel(const float* __restrict__ X,
                  const float* __restrict__ W1,
                  const float* __restrict__ b1) {
    __shared__ float As[BK][BM + 4];
    __shared__ float Bs[BK][BN];
    __shared__ int   s_tok[BM];

    int e    = blockIdx.z;
    int base = g_offset[e];
    int cnt  = g_offset[e+1] - base;
    int m0   = blockIdx.y * BM;
    if (m0 >= cnt) return;
    int n0   = blockIdx.x * BN;
    int tid  = threadIdx.x;

    if (tid < BM) {
        int r = m0 + tid;
        s_tok[tid] = (r < cnt) ? g_assign_tok[base + r] : -1;
    }
    __syncthreads();

    int tx = tid & 15, ty = tid >> 4;
    int ar = tid >> 2, ac = (tid & 3) * 4;   // A loader: row, k-offset
    int bk = tid >> 4, bn = (tid & 15) * 4;  // B loader

    int atok = s_tok[ar];
    const float* Arow  = X + (size_t)((atok >= 0) ? atok : 0) * D_MOD;
    const float* Bbase = W1 + (size_t)e * D_MOD * H_HID + n0;

    float acc[4][4];
#pragma unroll
    for (int i = 0; i < 4; i++)
#pragma unroll
        for (int j = 0; j < 4; j++) acc[i][j] = 0.f;

    for (int k0 = 0; k0 < D_MOD; k0 += BK) {
        float4 av = make_float4(0.f, 0.f, 0.f, 0.f);
        if (atok >= 0) av = *(const float4*)(Arow + k0 + ac);
        As[ac+0][ar] = av.x; As[ac+1][ar] = av.y;
        As[ac+2][ar] = av.z; As[ac+3][ar] = av.w;
        *(float4*)&Bs[bk][bn] =
            *(const float4*)(Bbase + (size_t)(k0 + bk) * H_HID + bn);
        __syncthreads();
#pragma unroll
        for (int kk = 0; kk < BK; kk++) {
            float4 a = *(const float4*)&As[kk][ty*4];
            float4 b = *(const float4*)&Bs[kk][tx*4];
            acc[0][0] += a.x*b.x; acc[0][1] += a.x*b.y; acc[0][2] += a.x*b.z; acc[0][3] += a.x*b.w;
            acc[1][0] += a.y*b.x; acc[1][1] += a.y*b.y; acc[1][2] += a.y*b.z; acc[1][3] += a.y*b.w;
            acc[2][0] += a.z*b.x; acc[2][1] += a.z*b.y; acc[2][2] += a.z*b.z; acc[2][3] += a.z*b.w;
            acc[3][0] += a.w*b.x; acc[3][1] += a.w*b.y; acc[3][2] += a.w*b.z; acc[3][3] += a.w*b.w;
        }
        __syncthreads();
    }

#pragma unroll
    for (int i = 0; i < 4; i++) {
        int r = m0 + ty*4 + i;
        if (r < cnt) {
            float* Hrow = g_Hbuf + (size_t)(base + r) * H_HID + n0 + tx*4;
#pragma unroll
            for (int j = 0; j < 4; j++) {
                float v = acc[i][j] + b1[e*H_HID + n0 + tx*4 + j];
                float u = 0.7978845608028654f * (v + 0.044715f*v*v*v);
                Hrow[j] = 0.5f * v * (1.f + tanhf(u));   // JAX gelu(approximate=True)
            }
        }
    }
}

// -------- FFN2: out += w * (H @ W2[e] + b2[e]) --------
__global__ __launch_bounds__(256)
void gemm2_kernel(const float* __restrict__ W2,
                  const float* __restrict__ b2,
                  float* __restrict__ out) {
    __shared__ float As[BK][BM + 4];
    __shared__ float Bs[BK][BN];
    __shared__ int   s_tok[BM];
    __shared__ float s_w[BM];

    int e    = blockIdx.z;
    int base = g_offset[e];
    int cnt  = g_offset[e+1] - base;
    int m0   = blockIdx.y * BM;
    if (m0 >= cnt) return;
    int n0   = blockIdx.x * BN;
    int tid  = threadIdx.x;

    if (tid < BM) {
        int r = m0 + tid;
        if (r < cnt) { s_tok[tid] = g_assign_tok[base + r]; s_w[tid] = g_assign_w[base + r]; }
        else         { s_tok[tid] = -1; s_w[tid] = 0.f; }
    }
    __syncthreads();

    int tx = tid & 15, ty = tid >> 4;
    int ar = tid >> 2, ac = (tid & 3) * 4;
    int bk = tid >> 4, bn = (tid & 15) * 4;

    int arow = m0 + ar;
    if (arow >= cnt) arow = cnt - 1;            // clamp: stay in-bounds, stores guarded
    const float* Arow  = g_Hbuf + (size_t)(base + arow) * H_HID;
    const float* Bbase = W2 + (size_t)e * H_HID * D_MOD + n0;

    float acc[4][4];
#pragma unroll
    for (int i = 0; i < 4; i++)
#pragma unroll
        for (int j = 0; j < 4; j++) acc[i][j] = 0.f;

    for (int k0 = 0; k0 < H_HID; k0 += BK) {
        float4 av = *(const float4*)(Arow + k0 + ac);
        As[ac+0][ar] = av.x; As[ac+1][ar] = av.y;
        As[ac+2][ar] = av.z; As[ac+3][ar] = av.w;
        *(float4*)&Bs[bk][bn] =
            *(const float4*)(Bbase + (size_t)(k0 + bk) * D_MOD + bn);
        __syncthreads();
#pragma unroll
        for (int kk = 0; kk < BK; kk++) {
            float4 a = *(const float4*)&As[kk][ty*4];
            float4 b = *(const float4*)&Bs[kk][tx*4];
            acc[0][0] += a.x*b.x; acc[0][1] += a.x*b.y; acc[0][2] += a.x*b.z; acc[0][3] += a.x*b.w;
            acc[1][0] += a.y*b.x; acc[1][1] += a.y*b.y; acc[1][2] += a.y*b.z; acc[1][3] += a.y*b.w;
            acc[2][0] += a.z*b.x; acc[2][1] += a.z*b.y; acc[2][2] += a.z*b.z; acc[2][3] += a.z*b.w;
            acc[3][0] += a.w*b.x; acc[3][1] += a.w*b.y; acc[3][2] += a.w*b.z; acc[3][3] += a.w*b.w;
        }
        __syncthreads();
    }

#pragma unroll
    for (int i = 0; i < 4; i++) {
        int r = m0 + ty*4 + i;
        if (r < cnt) {
            int   tok = s_tok[ty*4 + i];
            float w   = s_w[ty*4 + i];
            float* orow = out + (size_t)tok * D_MOD + n0 + tx*4;
#pragma unroll
            for (int j = 0; j < 4; j++) {
                float y = acc[i][j] + b2[e*D_MOD + n0 + tx*4 + j];
                atomicAdd(&orow[j], w * y);   // exactly 2 adds/elem -> commutative, deterministic
            }
        }
    }
}

// -------- launch --------
extern "C" void kernel_launch(void* const* d_in, const int* in_sizes, int n_in,
                              void* d_out, int out_size) {
    const float* X  = (const float*)d_in[0];  // [T, D]
    const float* Wg = (const float*)d_in[1];  // [D, E]
    const float* bg = (const float*)d_in[2];  // [E]
    const float* W1 = (const float*)d_in[3];  // [E, D, H]
    const float* b1 = (const float*)d_in[4];  // [E, H]
    const float* W2 = (const float*)d_in[5];  // [E, H, D]
    const float* b2 = (const float*)d_in[6];  // [E, D]
    (void)in_sizes; (void)n_in;

    float* out = (float*)d_out;
    float* out_idx = (out_size >= T_TOK*D_MOD + TOPK*T_TOK) ? out + T_TOK*D_MOD
                                                            : nullptr;

    init_kernel<<<2048, 256>>>(out);
    gate_kernel<<<T_TOK/8, 256>>>(X, Wg, bg, out_idx);
    offsets_kernel<<<1, 32>>>();
    scatter_kernel<<<T_TOK/256, 256>>>();

    // worst case one expert holds all 2048 tokens -> 32 row tiles
    dim3 g1(H_HID/BN, 2048/BM, N_EXP);
    gemm1_kernel<<<g1, 256>>>(X, W1, b1);
    dim3 g2(D_MOD/BN, 2048/BM, N_EXP);
    gemm2_kernel<<<g2, 256>>>(W2, b2, out);
}

// round 5
// speedup vs baseline: 3.1527x; 3.1527x over previous
#include <cuda_runtime.h>
#include <math.h>
#include <stdint.h>

// Problem constants
#define T_TOK 2048
#define D_MOD 1024
#define N_EXP 8
#define H_HID 2048
#define TOPK  2
#define NA    (T_TOK*TOPK)   // 4096 assignments

// GEMM tiling
#define BM 128
#define BN 128
#define BK 16

// -------- device scratch (no cudaMalloc allowed) --------
__device__ int   g_count[N_EXP];
__device__ int   g_offset[N_EXP+1];
__device__ int   g_cursor[N_EXP];
__device__ int   g_tok_e[NA];
__device__ float g_tok_w[NA];
__device__ int   g_assign_tok[NA];
__device__ float g_assign_w[NA];
__device__ float g_Hbuf[(size_t)NA * H_HID]; // 32 MB hidden activations

// -------- init --------
__global__ void init_kernel(float* __restrict__ out) {
    int total4 = (T_TOK * D_MOD) / 4;
    float4 z = make_float4(0.f, 0.f, 0.f, 0.f);
    for (int i = blockIdx.x * blockDim.x + threadIdx.x; i < total4;
         i += gridDim.x * blockDim.x) {
        reinterpret_cast<float4*>(out)[i] = z;
    }
    if (blockIdx.x == 0 && threadIdx.x < N_EXP) {
        g_count[threadIdx.x]  = 0;
        g_cursor[threadIdx.x] = 0;
    }
}

// -------- gate: logits, top-2, softmax --------
__global__ void gate_kernel(const float* __restrict__ X,
                            const float* __restrict__ Wg,
                            const float* __restrict__ bg,
                            float* __restrict__ out_idx) {
    int warp = (blockIdx.x * blockDim.x + threadIdx.x) >> 5;
    int lane = threadIdx.x & 31;
    if (warp >= T_TOK) return;
    const float* xr = X + (size_t)warp * D_MOD;

    float acc[N_EXP];
#pragma unroll
    for (int e = 0; e < N_EXP; e++) acc[e] = 0.f;

    for (int i = lane; i < D_MOD; i += 32) {
        float xv = xr[i];
        const float* wr = Wg + (size_t)i * N_EXP;
#pragma unroll
        for (int e = 0; e < N_EXP; e++) acc[e] += xv * wr[e];
    }
#pragma unroll
    for (int e = 0; e < N_EXP; e++) {
#pragma unroll
        for (int o = 16; o > 0; o >>= 1)
            acc[e] += __shfl_xor_sync(0xFFFFFFFFu, acc[e], o);
    }

    if (lane == 0) {
        float l[N_EXP];
#pragma unroll
        for (int e = 0; e < N_EXP; e++) l[e] = acc[e] + bg[e];

        float v0 = -1e30f, v1 = -1e30f;
        int   i0 = 0,      i1 = 0;
#pragma unroll
        for (int e = 0; e < N_EXP; e++) {
            if (l[e] > v0)      { v1 = v0; i1 = i0; v0 = l[e]; i0 = e; }
            else if (l[e] > v1) { v1 = l[e]; i1 = e; }
        }
        float s  = expf(v1 - v0);
        float w0 = 1.f / (1.f + s);
        float w1 = s * w0;

        int t = warp;
        g_tok_e[t*2+0] = i0;  g_tok_w[t*2+0] = w0;
        g_tok_e[t*2+1] = i1;  g_tok_w[t*2+1] = w1;
        atomicAdd(&g_count[i0], 1);
        atomicAdd(&g_count[i1], 1);
        if (out_idx) {
            out_idx[t*2+0] = (float)i0;
            out_idx[t*2+1] = (float)i1;
        }
    }
}

__global__ void offsets_kernel() {
    if (threadIdx.x == 0 && blockIdx.x == 0) {
        int run = 0;
        g_offset[0] = 0;
#pragma unroll
        for (int e = 0; e < N_EXP; e++) { run += g_count[e]; g_offset[e+1] = run; }
    }
}

__global__ void scatter_kernel() {
    int t = blockIdx.x * blockDim.x + threadIdx.x;
    if (t >= T_TOK) return;
#pragma unroll
    for (int j = 0; j < TOPK; j++) {
        int e = g_tok_e[t*2+j];
        int pos = atomicAdd(&g_cursor[e], 1);
        int slot = g_offset[e] + pos;
        g_assign_tok[slot] = t;
        g_assign_w[slot]   = g_tok_w[t*2+j];
    }
}

// -------- tf32 helpers --------
__device__ __forceinline__ uint32_t f2tf(float x) {
    uint32_t r;
    asm("cvt.rna.tf32.f32 %0, %1;" : "=r"(r) : "f"(x));
    return r;
}
__device__ __forceinline__ uint4 cvt4(float4 v) {
    uint4 u;
    u.x = f2tf(v.x); u.y = f2tf(v.y); u.z = f2tf(v.z); u.w = f2tf(v.w);
    return u;
}
__device__ __forceinline__ void mma8(float* d, const uint32_t* a, const uint32_t* b) {
    asm volatile(
        "mma.sync.aligned.m16n8k8.row.col.f32.tf32.tf32.f32 "
        "{%0,%1,%2,%3},{%4,%5,%6,%7},{%8,%9},{%0,%1,%2,%3};\n"
        : "+f"(d[0]), "+f"(d[1]), "+f"(d[2]), "+f"(d[3])
        : "r"(a[0]), "r"(a[1]), "r"(a[2]), "r"(a[3]), "r"(b[0]), "r"(b[1]));
}

// smem strides (bank-conflict-free vs m16n8k8 fragment pattern)
#define ASTRIDE 20    // A is m-major: As[row][k], row stride 20 (pad 4)
#define BSTRIDE 136   // B is k-major: Bs[k][n],  k stride 136 (pad 8)

// -------- FFN1: H = gelu(Xg @ W1[e] + b1[e]) (tf32 tensor cores) --------
__global__ __launch_bounds__(256)
void gemm1_kernel(const float* __restrict__ X,
                  const float* __restrict__ W1,
                  const float* __restrict__ b1) {
    __shared__ uint32_t As[2][BM][ASTRIDE];
    __shared__ uint32_t Bs[2][BK][BSTRIDE];
    __shared__ int s_tok[BM];

    int e    = blockIdx.z;
    int base = g_offset[e];
    int cnt  = g_offset[e+1] - base;
    int m0   = blockIdx.y * BM;
    if (m0 >= cnt) return;
    int n0   = blockIdx.x * BN;
    int tid  = threadIdx.x;

    if (tid < BM) {
        int r = m0 + tid;
        s_tok[tid] = g_assign_tok[base + ((r < cnt) ? r : 0)];
    }
    __syncthreads();

    int lane = tid & 31, warp = tid >> 5;
    int wm = warp & 3, wn = warp >> 2;

    // A loader: 2 float4 per thread per iter
    int ar0 = tid >> 2;           // rows 0..63
    int ar1 = ar0 + 64;           // rows 64..127
    int aq  = (tid & 3) * 4;      // k offset within BK
    const float* pA0 = X + (size_t)s_tok[ar0] * D_MOD + aq;
    const float* pA1 = X + (size_t)s_tok[ar1] * D_MOD + aq;
    // B loader: 2 float4 per thread per iter
    int bk0 = tid >> 5;           // 0..7
    int bn0 = (tid & 31) * 4;
    const float* pB = W1 + (size_t)e * D_MOD * H_HID + n0 + bn0;

    float4 ra0, ra1, rb0, rb1;
    ra0 = *(const float4*)(pA0);
    ra1 = *(const float4*)(pA1);
    rb0 = *(const float4*)(pB + (size_t)bk0 * H_HID);
    rb1 = *(const float4*)(pB + (size_t)(bk0 + 8) * H_HID);

    *(uint4*)&As[0][ar0][aq]     = cvt4(ra0);
    *(uint4*)&As[0][ar1][aq]     = cvt4(ra1);
    *(uint4*)&Bs[0][bk0][bn0]    = cvt4(rb0);
    *(uint4*)&Bs[0][bk0+8][bn0]  = cvt4(rb1);
    __syncthreads();

    float acc[2][8][4];
#pragma unroll
    for (int mt = 0; mt < 2; mt++)
#pragma unroll
        for (int nt = 0; nt < 8; nt++)
#pragma unroll
            for (int j = 0; j < 4; j++) acc[mt][nt][j] = 0.f;

    const int nit = D_MOD / BK; // 64
    int buf = 0;
    for (int it = 0; it < nit; ++it) {
        int k0n = (it + 1) * BK;
        if (it + 1 < nit) {
            ra0 = *(const float4*)(pA0 + k0n);
            ra1 = *(const float4*)(pA1 + k0n);
            rb0 = *(const float4*)(pB + (size_t)(k0n + bk0) * H_HID);
            rb1 = *(const float4*)(pB + (size_t)(k0n + bk0 + 8) * H_HID);
        }
#pragma unroll
        for (int s = 0; s < 2; ++s) {
            uint32_t afr[2][4], bfr[8][2];
            int c = s * 8 + (lane & 3);
#pragma unroll
            for (int mt = 0; mt < 2; ++mt) {
                int r = wm * 32 + mt * 16 + (lane >> 2);
                afr[mt][0] = As[buf][r][c];
                afr[mt][1] = As[buf][r + 8][c];
                afr[mt][2] = As[buf][r][c + 4];
                afr[mt][3] = As[buf][r + 8][c + 4];
            }
#pragma unroll
            for (int nt = 0; nt < 8; ++nt) {
                int n = wn * 64 + nt * 8 + (lane >> 2);
                bfr[nt][0] = Bs[buf][c][n];
                bfr[nt][1] = Bs[buf][c + 4][n];
            }
#pragma unroll
            for (int mt = 0; mt < 2; ++mt)
#pragma unroll
                for (int nt = 0; nt < 8; ++nt)
                    mma8(acc[mt][nt], afr[mt], bfr[nt]);
        }
        if (it + 1 < nit) {
            buf ^= 1;
            *(uint4*)&As[buf][ar0][aq]    = cvt4(ra0);
            *(uint4*)&As[buf][ar1][aq]    = cvt4(ra1);
            *(uint4*)&Bs[buf][bk0][bn0]   = cvt4(rb0);
            *(uint4*)&Bs[buf][bk0+8][bn0] = cvt4(rb1);
        }
        __syncthreads();
    }

    // epilogue: bias + gelu(tanh) -> Hbuf
#pragma unroll
    for (int mt = 0; mt < 2; ++mt) {
        int rt0 = wm * 32 + mt * 16 + (lane >> 2);
#pragma unroll
        for (int half = 0; half < 2; ++half) {
            int r = m0 + rt0 + half * 8;
            if (r < cnt) {
                float* Hrow = g_Hbuf + (size_t)(base + r) * H_HID + n0 + wn * 64;
                const float* brow = b1 + e * H_HID + n0 + wn * 64;
#pragma unroll
                for (int nt = 0; nt < 8; ++nt) {
                    int cc = nt * 8 + (lane & 3) * 2;
                    float v0 = acc[mt][nt][half * 2 + 0] + brow[cc];
                    float v1 = acc[mt][nt][half * 2 + 1] + brow[cc + 1];
                    float u0 = 0.7978845608028654f * (v0 + 0.044715f * v0 * v0 * v0);
                    float u1 = 0.7978845608028654f * (v1 + 0.044715f * v1 * v1 * v1);
                    float g0 = 0.5f * v0 * (1.f + tanhf(u0));
                    float g1 = 0.5f * v1 * (1.f + tanhf(u1));
                    *(float2*)(Hrow + cc) = make_float2(g0, g1);
                }
            }
        }
    }
}

// -------- FFN2: out += w * (H @ W2[e] + b2[e]) (tf32 tensor cores) --------
__global__ __launch_bounds__(256)
void gemm2_kernel(const float* __restrict__ W2,
                  const float* __restrict__ b2,
                  float* __restrict__ out) {
    __shared__ uint32_t As[2][BM][ASTRIDE];
    __shared__ uint32_t Bs[2][BK][BSTRIDE];
    __shared__ int   s_tok[BM];
    __shared__ float s_w[BM];

    int e    = blockIdx.z;
    int base = g_offset[e];
    int cnt  = g_offset[e+1] - base;
    int m0   = blockIdx.y * BM;
    if (m0 >= cnt) return;
    int n0   = blockIdx.x * BN;
    int tid  = threadIdx.x;

    if (tid < BM) {
        int r = m0 + tid;
        if (r < cnt) { s_tok[tid] = g_assign_tok[base + r]; s_w[tid] = g_assign_w[base + r]; }
        else         { s_tok[tid] = -1; s_w[tid] = 0.f; }
    }
    __syncthreads();

    int lane = tid & 31, warp = tid >> 5;
    int wm = warp & 3, wn = warp >> 2;

    int ar0 = tid >> 2;
    int ar1 = ar0 + 64;
    int aq  = (tid & 3) * 4;
    int sr0 = m0 + ar0; if (sr0 >= cnt) sr0 = cnt - 1;  // clamp (stores guarded)
    int sr1 = m0 + ar1; if (sr1 >= cnt) sr1 = cnt - 1;
    const float* pA0 = g_Hbuf + (size_t)(base + sr0) * H_HID + aq;
    const float* pA1 = g_Hbuf + (size_t)(base + sr1) * H_HID + aq;
    int bk0 = tid >> 5;
    int bn0 = (tid & 31) * 4;
    const float* pB = W2 + (size_t)e * H_HID * D_MOD + n0 + bn0;

    float4 ra0, ra1, rb0, rb1;
    ra0 = *(const float4*)(pA0);
    ra1 = *(const float4*)(pA1);
    rb0 = *(const float4*)(pB + (size_t)bk0 * D_MOD);
    rb1 = *(const float4*)(pB + (size_t)(bk0 + 8) * D_MOD);

    *(uint4*)&As[0][ar0][aq]     = cvt4(ra0);
    *(uint4*)&As[0][ar1][aq]     = cvt4(ra1);
    *(uint4*)&Bs[0][bk0][bn0]    = cvt4(rb0);
    *(uint4*)&Bs[0][bk0+8][bn0]  = cvt4(rb1);
    __syncthreads();

    float acc[2][8][4];
#pragma unroll
    for (int mt = 0; mt < 2; mt++)
#pragma unroll
        for (int nt = 0; nt < 8; nt++)
#pragma unroll
            for (int j = 0; j < 4; j++) acc[mt][nt][j] = 0.f;

    const int nit = H_HID / BK; // 128
    int buf = 0;
    for (int it = 0; it < nit; ++it) {
        int k0n = (it + 1) * BK;
        if (it + 1 < nit) {
            ra0 = *(const float4*)(pA0 + k0n);
            ra1 = *(const float4*)(pA1 + k0n);
            rb0 = *(const float4*)(pB + (size_t)(k0n + bk0) * D_MOD);
            rb1 = *(const float4*)(pB + (size_t)(k0n + bk0 + 8) * D_MOD);
        }
#pragma unroll
        for (int s = 0; s < 2; ++s) {
            uint32_t afr[2][4], bfr[8][2];
            int c = s * 8 + (lane & 3);
#pragma unroll
            for (int mt = 0; mt < 2; ++mt) {
                int r = wm * 32 + mt * 16 + (lane >> 2);
                afr[mt][0] = As[buf][r][c];
                afr[mt][1] = As[buf][r + 8][c];
                afr[mt][2] = As[buf][r][c + 4];
                afr[mt][3] = As[buf][r + 8][c + 4];
            }
#pragma unroll
            for (int nt = 0; nt < 8; ++nt) {
                int n = wn * 64 + nt * 8 + (lane >> 2);
                bfr[nt][0] = Bs[buf][c][n];
                bfr[nt][1] = Bs[buf][c + 4][n];
            }
#pragma unroll
            for (int mt = 0; mt < 2; ++mt)
#pragma unroll
                for (int nt = 0; nt < 8; ++nt)
                    mma8(acc[mt][nt], afr[mt], bfr[nt]);
        }
        if (it + 1 < nit) {
            buf ^= 1;
            *(uint4*)&As[buf][ar0][aq]    = cvt4(ra0);
            *(uint4*)&As[buf][ar1][aq]    = cvt4(ra1);
            *(uint4*)&Bs[buf][bk0][bn0]   = cvt4(rb0);
            *(uint4*)&Bs[buf][bk0+8][bn0] = cvt4(rb1);
        }
        __syncthreads();
    }

    // epilogue: bias, gate-weight scale, atomic combine
#pragma unroll
    for (int mt = 0; mt < 2; ++mt) {
        int rt0 = wm * 32 + mt * 16 + (lane >> 2);
#pragma unroll
        for (int half = 0; half < 2; ++half) {
            int rtile = rt0 + half * 8;
            int r = m0 + rtile;
            if (r < cnt) {
                int   tok = s_tok[rtile];
                float w   = s_w[rtile];
                float* orow = out + (size_t)tok * D_MOD + n0 + wn * 64;
                const float* brow = b2 + e * D_MOD + n0 + wn * 64;
#pragma unroll
                for (int nt = 0; nt < 8; ++nt) {
                    int cc = nt * 8 + (lane & 3) * 2;
                    float y0 = acc[mt][nt][half * 2 + 0] + brow[cc];
                    float y1 = acc[mt][nt][half * 2 + 1] + brow[cc + 1];
                    atomicAdd(&orow[cc],     w * y0);
                    atomicAdd(&orow[cc + 1], w * y1);
                }
            }
        }
    }
}

// -------- launch --------
extern "C" void kernel_launch(void* const* d_in, const int* in_sizes, int n_in,
                              void* d_out, int out_size) {
    const float* X  = (const float*)d_in[0];
    const float* Wg = (const float*)d_in[1];
    const float* bg = (const float*)d_in[2];
    const float* W1 = (const float*)d_in[3];
    const float* b1 = (const float*)d_in[4];
    const float* W2 = (const float*)d_in[5];
    const float* b2 = (const float*)d_in[6];
    (void)in_sizes; (void)n_in;

    float* out = (float*)d_out;
    float* out_idx = (out_size >= T_TOK*D_MOD + TOPK*T_TOK) ? out + T_TOK*D_MOD
                                                            : nullptr;

    init_kernel<<<2048, 256>>>(out);
    gate_kernel<<<T_TOK/8, 256>>>(X, Wg, bg, out_idx);
    offsets_kernel<<<1, 32>>>();
    scatter_kernel<<<T_TOK/256, 256>>>();

    dim3 g1(H_HID/BN, T_TOK/BM, N_EXP);   // 16 x 16 x 8
    gemm1_kernel<<<g1, 256>>>(X, W1, b1);
    dim3 g2(D_MOD/BN, T_TOK/BM, N_EXP);   // 8 x 16 x 8
    gemm2_kernel<<<g2, 256>>>(W2, b2, out);
}

// round 7
// speedup vs baseline: 4.2202x; 1.3386x over previous
#include <cuda_runtime.h>
#include <cuda_fp16.h>
#include <math.h>
#include <stdint.h>

// Problem constants
#define T_TOK 2048
#define D_MOD 1024
#define N_EXP 8
#define H_HID 2048
#define TOPK  2
#define NA    (T_TOK*TOPK)   // 4096 assignments

// GEMM tiling
#define BM 128
#define BN 128
#define BK 16

// -------- device scratch (no cudaMalloc allowed) --------
__device__ int    g_count[N_EXP];
__device__ int    g_offset[N_EXP+1];
__device__ int    g_cursor[N_EXP];
__device__ int    g_tok_e[NA];
__device__ float  g_tok_w[NA];
__device__ int    g_assign_tok[NA];
__device__ float  g_assign_w[NA];
__device__ __half g_Hbuf[(size_t)NA * H_HID]; // 16 MB hidden activations (fp16)

// -------- init --------
__global__ void init_kernel(float* __restrict__ out) {
    int total4 = (T_TOK * D_MOD) / 4;
    float4 z = make_float4(0.f, 0.f, 0.f, 0.f);
    for (int i = blockIdx.x * blockDim.x + threadIdx.x; i < total4;
         i += gridDim.x * blockDim.x) {
        reinterpret_cast<float4*>(out)[i] = z;
    }
    if (blockIdx.x == 0 && threadIdx.x < N_EXP) {
        g_count[threadIdx.x]  = 0;
        g_cursor[threadIdx.x] = 0;
    }
}

// -------- gate: logits, top-2, softmax --------
__global__ void gate_kernel(const float* __restrict__ X,
                            const float* __restrict__ Wg,
                            const float* __restrict__ bg,
                            float* __restrict__ out_idx) {
    int warp = (blockIdx.x * blockDim.x + threadIdx.x) >> 5;
    int lane = threadIdx.x & 31;
    if (warp >= T_TOK) return;
    const float* xr = X + (size_t)warp * D_MOD;

    float acc[N_EXP];
#pragma unroll
    for (int e = 0; e < N_EXP; e++) acc[e] = 0.f;

    for (int i = lane; i < D_MOD; i += 32) {
        float xv = xr[i];
        const float* wr = Wg + (size_t)i * N_EXP;
#pragma unroll
        for (int e = 0; e < N_EXP; e++) acc[e] += xv * wr[e];
    }
#pragma unroll
    for (int e = 0; e < N_EXP; e++) {
#pragma unroll
        for (int o = 16; o > 0; o >>= 1)
            acc[e] += __shfl_xor_sync(0xFFFFFFFFu, acc[e], o);
    }

    if (lane == 0) {
        float l[N_EXP];
#pragma unroll
        for (int e = 0; e < N_EXP; e++) l[e] = acc[e] + bg[e];

        float v0 = -1e30f, v1 = -1e30f;
        int   i0 = 0,      i1 = 0;
#pragma unroll
        for (int e = 0; e < N_EXP; e++) {
            if (l[e] > v0)      { v1 = v0; i1 = i0; v0 = l[e]; i0 = e; }
            else if (l[e] > v1) { v1 = l[e]; i1 = e; }
        }
        float s  = expf(v1 - v0);
        float w0 = 1.f / (1.f + s);
        float w1 = s * w0;

        int t = warp;
        g_tok_e[t*2+0] = i0;  g_tok_w[t*2+0] = w0;
        g_tok_e[t*2+1] = i1;  g_tok_w[t*2+1] = w1;
        atomicAdd(&g_count[i0], 1);
        atomicAdd(&g_count[i1], 1);
        if (out_idx) {
            out_idx[t*2+0] = (float)i0;
            out_idx[t*2+1] = (float)i1;
        }
    }
}

__global__ void offsets_kernel() {
    if (threadIdx.x == 0 && blockIdx.x == 0) {
        int run = 0;
        g_offset[0] = 0;
#pragma unroll
        for (int e = 0; e < N_EXP; e++) { run += g_count[e]; g_offset[e+1] = run; }
    }
}

__global__ void scatter_kernel() {
    int t = blockIdx.x * blockDim.x + threadIdx.x;
    if (t >= T_TOK) return;
#pragma unroll
    for (int j = 0; j < TOPK; j++) {
        int e = g_tok_e[t*2+j];
        int pos = atomicAdd(&g_cursor[e], 1);
        int slot = g_offset[e] + pos;
        g_assign_tok[slot] = t;
        g_assign_w[slot]   = g_tok_w[t*2+j];
    }
}

// -------- fp16 helpers --------
__device__ __forceinline__ uint32_t packh(float lo, float hi) {
    __half2 h = __floats2half2_rn(lo, hi);
    return *reinterpret_cast<uint32_t*>(&h);
}
__device__ __forceinline__ void mma16(float* d, const uint32_t* a, const uint32_t* b) {
    asm volatile(
        "mma.sync.aligned.m16n8k16.row.col.f32.f16.f16.f32 "
        "{%0,%1,%2,%3},{%4,%5,%6,%7},{%8,%9},{%0,%1,%2,%3};\n"
        : "+f"(d[0]), "+f"(d[1]), "+f"(d[2]), "+f"(d[3])
        : "r"(a[0]), "r"(a[1]), "r"(a[2]), "r"(a[3]), "r"(b[0]), "r"(b[1]));
}

// smem strides (uint32 units; each uint32 = packed k-pair of halves)
#define ASTR 12    // A: As[row][kpair], 8 kpairs + pad -> fragment reads conflict-free
#define BSTR 136   // B: Bs[kpair][n], 128 n + pad    -> conflict-free both ways

// ============ FFN1: H = gelu(Xg @ W1[e] + b1[e]) (fp16 tensor cores) ============
__global__ __launch_bounds__(256)
void gemm1_kernel(const float* __restrict__ X,
                  const float* __restrict__ W1,
                  const float* __restrict__ b1) {
    __shared__ uint32_t As[2][BM][ASTR];
    __shared__ uint32_t Bs[2][BK/2][BSTR];
    __shared__ int s_tok[BM];

    int e    = blockIdx.z;
    int base = g_offset[e];
    int cnt  = g_offset[e+1] - base;
    int m0   = blockIdx.y * BM;
    if (m0 >= cnt) return;
    int n0   = blockIdx.x * BN;
    int tid  = threadIdx.x;

    if (tid < BM) {
        int r = m0 + tid;
        s_tok[tid] = g_assign_tok[base + ((r < cnt) ? r : 0)];
    }
    __syncthreads();

    int lane = tid & 31, warp = tid >> 5;
    int wm = warp & 3, wn = warp >> 2;

    // A loader: row = tid>>1 (0..127), kh = (tid&1)*8 (k offset in floats)
    int arow = tid >> 1;
    int akh  = (tid & 1) * 8;
    const float* pA = X + (size_t)s_tok[arow] * D_MOD + akh;
    // B loader: kp = tid>>5 (0..7 -> k rows 2kp,2kp+1), n4 = (lane)*4
    int bkp = tid >> 5;
    int bn4 = (tid & 31) * 4;
    const float* pB = W1 + (size_t)e * D_MOD * H_HID + n0 + bn4;

    float4 ra0, ra1, rb0, rb1;
    ra0 = *(const float4*)(pA);
    ra1 = *(const float4*)(pA + 4);
    rb0 = *(const float4*)(pB + (size_t)(2*bkp)     * H_HID);
    rb1 = *(const float4*)(pB + (size_t)(2*bkp + 1) * H_HID);

    {
        uint32_t* as = &As[0][arow][akh >> 1];
        as[0] = packh(ra0.x, ra0.y); as[1] = packh(ra0.z, ra0.w);
        as[2] = packh(ra1.x, ra1.y); as[3] = packh(ra1.z, ra1.w);
        uint32_t* bs = &Bs[0][bkp][bn4];
        bs[0] = packh(rb0.x, rb1.x); bs[1] = packh(rb0.y, rb1.y);
        bs[2] = packh(rb0.z, rb1.z); bs[3] = packh(rb0.w, rb1.w);
    }
    __syncthreads();

    float acc[2][8][4];
#pragma unroll
    for (int mt = 0; mt < 2; mt++)
#pragma unroll
        for (int nt = 0; nt < 8; nt++)
#pragma unroll
            for (int j = 0; j < 4; j++) acc[mt][nt][j] = 0.f;

    const int nit = D_MOD / BK; // 64
    int buf = 0;
    for (int it = 0; it < nit; ++it) {
        int k0n = (it + 1) * BK;
        if (it + 1 < nit) {
            ra0 = *(const float4*)(pA + k0n);
            ra1 = *(const float4*)(pA + k0n + 4);
            rb0 = *(const float4*)(pB + (size_t)(k0n + 2*bkp)     * H_HID);
            rb1 = *(const float4*)(pB + (size_t)(k0n + 2*bkp + 1) * H_HID);
        }
        {
            uint32_t afr[2][4], bfr[8][2];
            int c = lane & 3;
#pragma unroll
            for (int mt = 0; mt < 2; ++mt) {
                int r = wm * 32 + mt * 16 + (lane >> 2);
                afr[mt][0] = As[buf][r][c];
                afr[mt][1] = As[buf][r + 8][c];
                afr[mt][2] = As[buf][r][c + 4];
                afr[mt][3] = As[buf][r + 8][c + 4];
            }
#pragma unroll
            for (int nt = 0; nt < 8; ++nt) {
                int n = wn * 64 + nt * 8 + (lane >> 2);
                bfr[nt][0] = Bs[buf][c][n];
                bfr[nt][1] = Bs[buf][c + 4][n];
            }
#pragma unroll
            for (int mt = 0; mt < 2; ++mt)
#pragma unroll
                for (int nt = 0; nt < 8; ++nt)
                    mma16(acc[mt][nt], afr[mt], bfr[nt]);
        }
        if (it + 1 < nit) {
            buf ^= 1;
            uint32_t* as = &As[buf][arow][akh >> 1];
            as[0] = packh(ra0.x, ra0.y); as[1] = packh(ra0.z, ra0.w);
            as[2] = packh(ra1.x, ra1.y); as[3] = packh(ra1.z, ra1.w);
            uint32_t* bs = &Bs[buf][bkp][bn4];
            bs[0] = packh(rb0.x, rb1.x); bs[1] = packh(rb0.y, rb1.y);
            bs[2] = packh(rb0.z, rb1.z); bs[3] = packh(rb0.w, rb1.w);
        }
        __syncthreads();
    }

    // epilogue: bias + gelu(tanh) -> Hbuf (fp16)
#pragma unroll
    for (int mt = 0; mt < 2; ++mt) {
        int rt0 = wm * 32 + mt * 16 + (lane >> 2);
#pragma unroll
        for (int half = 0; half < 2; ++half) {
            int r = m0 + rt0 + half * 8;
            if (r < cnt) {
                __half* Hrow = g_Hbuf + (size_t)(base + r) * H_HID + n0 + wn * 64;
                const float* brow = b1 + e * H_HID + n0 + wn * 64;
#pragma unroll
                for (int nt = 0; nt < 8; ++nt) {
                    int cc = nt * 8 + (lane & 3) * 2;
                    float v0 = acc[mt][nt][half * 2 + 0] + brow[cc];
                    float v1 = acc[mt][nt][half * 2 + 1] + brow[cc + 1];
                    float u0 = 0.7978845608028654f * (v0 + 0.044715f * v0 * v0 * v0);
                    float u1 = 0.7978845608028654f * (v1 + 0.044715f * v1 * v1 * v1);
                    float g0 = 0.5f * v0 * (1.f + tanhf(u0));
                    float g1 = 0.5f * v1 * (1.f + tanhf(u1));
                    *(__half2*)(Hrow + cc) = __floats2half2_rn(g0, g1);
                }
            }
        }
    }
}

// ============ FFN2: out += w * (H @ W2[e] + b2[e]) (fp16 tensor cores) ============
__global__ __launch_bounds__(256)
void gemm2_kernel(const float* __restrict__ W2,
                  const float* __restrict__ b2,
                  float* __restrict__ out) {
    __shared__ uint32_t As[2][BM][ASTR];
    __shared__ uint32_t Bs[2][BK/2][BSTR];
    __shared__ int   s_tok[BM];
    __shared__ float s_w[BM];

    int e    = blockIdx.z;
    int base = g_offset[e];
    int cnt  = g_offset[e+1] - base;
    int m0   = blockIdx.y * BM;
    if (m0 >= cnt) return;
    int n0   = blockIdx.x * BN;
    int tid  = threadIdx.x;

    if (tid < BM) {
        int r = m0 + tid;
        if (r < cnt) { s_tok[tid] = g_assign_tok[base + r]; s_w[tid] = g_assign_w[base + r]; }
        else         { s_tok[tid] = -1; s_w[tid] = 0.f; }
    }
    __syncthreads();

    int lane = tid & 31, warp = tid >> 5;
    int wm = warp & 3, wn = warp >> 2;

    // A loader: Hbuf already fp16 & k-pair packed -> raw uint4 copy
    int arow = tid >> 1;
    int akh  = (tid & 1) * 8;     // k offset in halves
    int sr = m0 + arow; if (sr >= cnt) sr = cnt - 1;   // clamp (stores guarded)
    const __half* pA = g_Hbuf + (size_t)(base + sr) * H_HID + akh;
    int bkp = tid >> 5;
    int bn4 = (tid & 31) * 4;
    const float* pB = W2 + (size_t)e * H_HID * D_MOD + n0 + bn4;

    uint4  ha;
    float4 rb0, rb1;
    ha  = *(const uint4*)(pA);
    rb0 = *(const float4*)(pB + (size_t)(2*bkp)     * D_MOD);
    rb1 = *(const float4*)(pB + (size_t)(2*bkp + 1) * D_MOD);

    {
        *(uint4*)&As[0][arow][akh >> 1] = ha;
        uint32_t* bs = &Bs[0][bkp][bn4];
        bs[0] = packh(rb0.x, rb1.x); bs[1] = packh(rb0.y, rb1.y);
        bs[2] = packh(rb0.z, rb1.z); bs[3] = packh(rb0.w, rb1.w);
    }
    __syncthreads();

    float acc[2][8][4];
#pragma unroll
    for (int mt = 0; mt < 2; mt++)
#pragma unroll
        for (int nt = 0; nt < 8; nt++)
#pragma unroll
            for (int j = 0; j < 4; j++) acc[mt][nt][j] = 0.f;

    const int nit = H_HID / BK; // 128
    int buf = 0;
    for (int it = 0; it < nit; ++it) {
        int k0n = (it + 1) * BK;
        if (it + 1 < nit) {
            ha  = *(const uint4*)(pA + k0n);
            rb0 = *(const float4*)(pB + (size_t)(k0n + 2*bkp)     * D_MOD);
            rb1 = *(const float4*)(pB + (size_t)(k0n + 2*bkp + 1) * D_MOD);
        }
        {
            uint32_t afr[2][4], bfr[8][2];
            int c = lane & 3;
#pragma unroll
            for (int mt = 0; mt < 2; ++mt) {
                int r = wm * 32 + mt * 16 + (lane >> 2);
                afr[mt][0] = As[buf][r][c];
                afr[mt][1] = As[buf][r + 8][c];
                afr[mt][2] = As[buf][r][c + 4];
                afr[mt][3] = As[buf][r + 8][c + 4];
            }
#pragma unroll
            for (int nt = 0; nt < 8; ++nt) {
                int n = wn * 64 + nt * 8 + (lane >> 2);
                bfr[nt][0] = Bs[buf][c][n];
                bfr[nt][1] = Bs[buf][c + 4][n];
            }
#pragma unroll
            for (int mt = 0; mt < 2; ++mt)
#pragma unroll
                for (int nt = 0; nt < 8; ++nt)
                    mma16(acc[mt][nt], afr[mt], bfr[nt]);
        }
        if (it + 1 < nit) {
            buf ^= 1;
            *(uint4*)&As[buf][arow][akh >> 1] = ha;
            uint32_t* bs = &Bs[buf][bkp][bn4];
            bs[0] = packh(rb0.x, rb1.x); bs[1] = packh(rb0.y, rb1.y);
            bs[2] = packh(rb0.z, rb1.z); bs[3] = packh(rb0.w, rb1.w);
        }
        __syncthreads();
    }

    // epilogue: bias, gate-weight scale, atomic combine
#pragma unroll
    for (int mt = 0; mt < 2; ++mt) {
        int rt0 = wm * 32 + mt * 16 + (lane >> 2);
#pragma unroll
        for (int half = 0; half < 2; ++half) {
            int rtile = rt0 + half * 8;
            int r = m0 + rtile;
            if (r < cnt) {
                int   tok = s_tok[rtile];
                float w   = s_w[rtile];
                float* orow = out + (size_t)tok * D_MOD + n0 + wn * 64;
                const float* brow = b2 + e * D_MOD + n0 + wn * 64;
#pragma unroll
                for (int nt = 0; nt < 8; ++nt) {
                    int cc = nt * 8 + (lane & 3) * 2;
                    float y0 = acc[mt][nt][half * 2 + 0] + brow[cc];
                    float y1 = acc[mt][nt][half * 2 + 1] + brow[cc + 1];
                    atomicAdd(&orow[cc],     w * y0);
                    atomicAdd(&orow[cc + 1], w * y1);
                }
            }
        }
    }
}

// -------- launch --------
extern "C" void kernel_launch(void* const* d_in, const int* in_sizes, int n_in,
                              void* d_out, int out_size) {
    const float* X  = (const float*)d_in[0];
    const float* Wg = (const float*)d_in[1];
    const float* bg = (const float*)d_in[2];
    const float* W1 = (const float*)d_in[3];
    const float* b1 = (const float*)d_in[4];
    const float* W2 = (const float*)d_in[5];
    const float* b2 = (const float*)d_in[6];
    (void)in_sizes; (void)n_in;

    float* out = (float*)d_out;
    float* out_idx = (out_size >= T_TOK*D_MOD + TOPK*T_TOK) ? out + T_TOK*D_MOD
                                                            : nullptr;

    init_kernel<<<2048, 256>>>(out);
    gate_kernel<<<T_TOK/8, 256>>>(X, Wg, bg, out_idx);
    offsets_kernel<<<1, 32>>>();
    scatter_kernel<<<T_TOK/256, 256>>>();

    dim3 g1(H_HID/BN, T_TOK/BM, N_EXP);   // 16 x 16 x 8
    gemm1_kernel<<<g1, 256>>>(X, W1, b1);
    dim3 g2(D_MOD/BN, T_TOK/BM, N_EXP);   // 8 x 16 x 8
    gemm2_kernel<<<g2, 256>>>(W2, b2, out);
}